// round 1
// baseline (speedup 1.0000x reference)
#include <cuda_runtime.h>
#include <cuda_bf16.h>
#include <math.h>

#define BATCH   32
#define DIM     4096
#define NKV     8
#define REP     4
#define HD      128
#define QKVN    6144      // (32 + 2*8) * 128
#define CL      2176      // cache length
#define NCH     17        // 17 * 128 = 2176
#define CH      128
#define KSPLIT  16
#define KCHUNK  256       // 4096 / 16

// ---------------- scratch (static device globals; no allocs allowed) ----------
__device__ float g_cos[64];
__device__ float g_sin[64];
__device__ float g_qkvp[KSPLIT * BATCH * QKVN];          // 12.6 MB
__device__ float g_q[BATCH * DIM];                       // 512 KB (b, g, r, d)
__device__ float g_k[BATCH * NKV * HD];
__device__ float g_v[BATCH * NKV * HD];
__device__ float g_pacc[(size_t)BATCH * NKV * NCH * REP * HD];  // 8.9 MB
__device__ float g_pm[BATCH * NKV * NCH * REP];
__device__ float g_pl[BATCH * NKV * NCH * REP];
__device__ float g_attn[BATCH * DIM];
__device__ float g_wop[KSPLIT * BATCH * DIM];            // 8.4 MB

// ---------------- RoPE table (double precision, tiny) -------------------------
__global__ void k_rope_table(const int* __restrict__ spp) {
    int i = threadIdx.x;
    if (i < 64) {
        int sp = *spp;
        double e    = (2.0 * (double)i) / 128.0;
        double invf = pow(10000.0, -e);
        double ang  = (double)sp * invf;
        g_cos[i] = (float)cos(ang);
        g_sin[i] = (float)sin(ang);
    }
}

// ---------------- QKV GEMM: out[32,6144] partials over K-splits ---------------
// grid (24, KSPLIT), 256 threads. Each thread owns one output column n for all
// 32 rows over a 256-wide K chunk.
__global__ __launch_bounds__(256) void k_qkv(const float* __restrict__ x,
                                             const float* __restrict__ w) {
    __shared__ __align__(16) float xs[BATCH * KCHUNK];   // 32 KB
    int t  = threadIdx.x;
    int k0 = blockIdx.y * KCHUNK;

    const float4* xg  = (const float4*)x;
    float4*       xs4 = (float4*)xs;
    #pragma unroll
    for (int it = 0; it < 8; it++) {                     // 2048 float4 total
        int j  = t + 256 * it;
        int m  = j >> 6;                                 // 64 float4 per row
        int c4 = j & 63;
        xs4[m * 64 + c4] = xg[m * (DIM / 4) + (k0 >> 2) + c4];
    }
    __syncthreads();

    int n = blockIdx.x * 256 + t;
    float acc[BATCH];
    #pragma unroll
    for (int m = 0; m < BATCH; m++) acc[m] = 0.f;

    const float* wp0 = w + (size_t)k0 * QKVN + n;
    #pragma unroll 2
    for (int c4 = 0; c4 < 64; c4++) {
        const float* wp = wp0 + (size_t)c4 * 4 * QKVN;
        float w0 = wp[0];
        float w1 = wp[QKVN];
        float w2 = wp[2 * QKVN];
        float w3 = wp[3 * QKVN];
        #pragma unroll
        for (int m = 0; m < BATCH; m++) {
            float4 xv = xs4[m * 64 + c4];
            acc[m] += xv.x * w0 + xv.y * w1 + xv.z * w2 + xv.w * w3;
        }
    }
    float* o = g_qkvp + (size_t)blockIdx.y * BATCH * QKVN + n;
    #pragma unroll
    for (int m = 0; m < BATCH; m++) o[m * QKVN] = acc[m];
}

// ---------------- reduce K-split partials + RoPE ------------------------------
__global__ __launch_bounds__(256) void k_reduce_rope() {
    int idx = blockIdx.x * 256 + threadIdx.x;            // < 32*6144
    int m = idx / QKVN;
    int n = idx % QKVN;

    float s = 0.f;
    #pragma unroll
    for (int p = 0; p < KSPLIT; p++) s += g_qkvp[((size_t)p * BATCH + m) * QKVN + n];

    if (n < 5120) {                                      // q or k: apply RoPE
        int d  = n & 127;
        int n2 = (d < 64) ? n + 64 : n - 64;
        float s2 = 0.f;
        #pragma unroll
        for (int p = 0; p < KSPLIT; p++) s2 += g_qkvp[((size_t)p * BATCH + m) * QKVN + n2];
        int i = d & 63;
        float out = (d < 64) ? s * g_cos[i] - s2 * g_sin[i]
                             : s * g_cos[i] + s2 * g_sin[i];
        if (n < 4096) g_q[m * DIM + n] = out;
        else          g_k[m * (NKV * HD) + (n - 4096)] = out;
    } else {
        g_v[m * (NKV * HD) + (n - 5120)] = s;
    }
}

// ---------------- flash-decode attention partials -----------------------------
// grid (NCH, 256): blockIdx.y = bg = b*8+g, blockIdx.x = chunk. 128 threads.
__global__ __launch_bounds__(128) void k_attn(const float* __restrict__ ck,
                                              const float* __restrict__ cv,
                                              const int* __restrict__ spp) {
    __shared__ __align__(16) float qs[REP * HD];         // 2 KB
    __shared__ __align__(16) float kt[64 * 132];         // 33.8 KB (K then V tiles)
    __shared__ float ps[REP * CH];                       // scores -> probs
    __shared__ float red_m[REP], red_l[REP];

    const int t  = threadIdx.x;
    const int c  = blockIdx.x;
    const int bg = blockIdx.y;
    const int sp = *spp;
    const float SCALE = 0.08838834764831845f;            // 1/sqrt(128)

    // load q (b, g): 512 floats
    #pragma unroll
    for (int it = 0; it < 4; it++) qs[t + 128 * it] = g_q[(size_t)bg * 512 + t + 128 * it];
    __syncthreads();

    // ---- score phase: two 64-row K tiles ----
    for (int tt = 0; tt < 2; tt++) {
        int s_base = c * CH + tt * 64;
        #pragma unroll
        for (int it = 0; it < 16; it++) {                // 2048 float4
            int j   = t + 128 * it;
            int row = j >> 5;
            int c4  = j & 31;
            int s   = s_base + row;
            float4 val;
            if (s == sp) val = ((const float4*)g_k)[bg * 32 + c4];
            else         val = ((const float4*)ck)[((size_t)bg * CL + s) * 32 + c4];
            *(float4*)&kt[row * 132 + c4 * 4] = val;
        }
        __syncthreads();
        if (t < 64) {
            float a0 = 0.f, a1 = 0.f, a2 = 0.f, a3 = 0.f;
            #pragma unroll
            for (int d4 = 0; d4 < 32; d4++) {
                float4 kv = *(const float4*)&kt[t * 132 + d4 * 4];
                float4 q0 = *(const float4*)&qs[0 * HD + d4 * 4];
                float4 q1 = *(const float4*)&qs[1 * HD + d4 * 4];
                float4 q2 = *(const float4*)&qs[2 * HD + d4 * 4];
                float4 q3 = *(const float4*)&qs[3 * HD + d4 * 4];
                a0 += kv.x * q0.x + kv.y * q0.y + kv.z * q0.z + kv.w * q0.w;
                a1 += kv.x * q1.x + kv.y * q1.y + kv.z * q1.z + kv.w * q1.w;
                a2 += kv.x * q2.x + kv.y * q2.y + kv.z * q2.z + kv.w * q2.w;
                a3 += kv.x * q3.x + kv.y * q3.y + kv.z * q3.z + kv.w * q3.w;
            }
            int  sg   = s_base + t;
            bool ok   = (sg <= sp);
            int  sloc = tt * 64 + t;
            ps[0 * CH + sloc] = ok ? a0 * SCALE : -1e9f;
            ps[1 * CH + sloc] = ok ? a1 * SCALE : -1e9f;
            ps[2 * CH + sloc] = ok ? a2 * SCALE : -1e9f;
            ps[3 * CH + sloc] = ok ? a3 * SCALE : -1e9f;
        }
        __syncthreads();
    }

    // ---- chunk softmax: warp w handles head-rep r = w ----
    {
        int w = t >> 5, l = t & 31;
        float v0 = ps[w * CH + l];
        float v1 = ps[w * CH + l + 32];
        float v2 = ps[w * CH + l + 64];
        float v3 = ps[w * CH + l + 96];
        float mx = fmaxf(fmaxf(v0, v1), fmaxf(v2, v3));
        #pragma unroll
        for (int off = 16; off > 0; off >>= 1)
            mx = fmaxf(mx, __shfl_xor_sync(0xffffffffu, mx, off));
        float e0 = expf(v0 - mx), e1 = expf(v1 - mx);
        float e2 = expf(v2 - mx), e3 = expf(v3 - mx);
        float sum = e0 + e1 + e2 + e3;
        #pragma unroll
        for (int off = 16; off > 0; off >>= 1)
            sum += __shfl_xor_sync(0xffffffffu, sum, off);
        ps[w * CH + l]      = e0;
        ps[w * CH + l + 32] = e1;
        ps[w * CH + l + 64] = e2;
        ps[w * CH + l + 96] = e3;
        if (l == 0) { red_m[w] = mx; red_l[w] = sum; }
    }
    __syncthreads();

    // ---- V phase: accumulate o[r][d], thread owns d = t ----
    float o0 = 0.f, o1 = 0.f, o2 = 0.f, o3 = 0.f;
    for (int tt = 0; tt < 2; tt++) {
        int s_base = c * CH + tt * 64;
        #pragma unroll
        for (int it = 0; it < 16; it++) {
            int j   = t + 128 * it;
            int row = j >> 5;
            int c4  = j & 31;
            int s   = s_base + row;
            float4 val;
            if (s == sp) val = ((const float4*)g_v)[bg * 32 + c4];
            else         val = ((const float4*)cv)[((size_t)bg * CL + s) * 32 + c4];
            *(float4*)&kt[row * 132 + c4 * 4] = val;
        }
        __syncthreads();
        #pragma unroll 8
        for (int s = 0; s < 64; s++) {
            float vv = kt[s * 132 + t];
            int   sl = tt * 64 + s;
            o0 += ps[0 * CH + sl] * vv;
            o1 += ps[1 * CH + sl] * vv;
            o2 += ps[2 * CH + sl] * vv;
            o3 += ps[3 * CH + sl] * vv;
        }
        __syncthreads();
    }

    size_t pb = ((size_t)bg * NCH + c) * REP;
    g_pacc[(pb + 0) * HD + t] = o0;
    g_pacc[(pb + 1) * HD + t] = o1;
    g_pacc[(pb + 2) * HD + t] = o2;
    g_pacc[(pb + 3) * HD + t] = o3;
    if (t < REP) { g_pm[pb + t] = red_m[t]; g_pl[pb + t] = red_l[t]; }
}

// ---------------- combine split-S partials ------------------------------------
__global__ __launch_bounds__(128) void k_combine() {
    __shared__ float ms[NCH * REP], ls[NCH * REP];
    int bg = blockIdx.x, t = threadIdx.x;
    if (t < NCH * REP) {
        ms[t] = g_pm[bg * NCH * REP + t];
        ls[t] = g_pl[bg * NCH * REP + t];
    }
    __syncthreads();
    #pragma unroll
    for (int r = 0; r < REP; r++) {
        float M = -1e30f;
        #pragma unroll
        for (int cc = 0; cc < NCH; cc++) M = fmaxf(M, ms[cc * REP + r]);
        float L = 0.f, val = 0.f;
        for (int cc = 0; cc < NCH; cc++) {
            float wgt = expf(ms[cc * REP + r] - M);
            L   += ls[cc * REP + r] * wgt;
            val += g_pacc[(((size_t)bg * NCH + cc) * REP + r) * HD + t] * wgt;
        }
        g_attn[(size_t)bg * 512 + r * HD + t] = val / L;
    }
}

// ---------------- WO GEMM: g_attn[32,4096] @ wo[4096,4096] --------------------
__global__ __launch_bounds__(256) void k_wo(const float* __restrict__ w) {
    __shared__ __align__(16) float xs[BATCH * KCHUNK];
    int t  = threadIdx.x;
    int k0 = blockIdx.y * KCHUNK;

    const float4* xg  = (const float4*)g_attn;
    float4*       xs4 = (float4*)xs;
    #pragma unroll
    for (int it = 0; it < 8; it++) {
        int j  = t + 256 * it;
        int m  = j >> 6;
        int c4 = j & 63;
        xs4[m * 64 + c4] = xg[m * (DIM / 4) + (k0 >> 2) + c4];
    }
    __syncthreads();

    int n = blockIdx.x * 256 + t;
    float acc[BATCH];
    #pragma unroll
    for (int m = 0; m < BATCH; m++) acc[m] = 0.f;

    const float* wp0 = w + (size_t)k0 * DIM + n;
    #pragma unroll 2
    for (int c4 = 0; c4 < 64; c4++) {
        const float* wp = wp0 + (size_t)c4 * 4 * DIM;
        float w0 = wp[0];
        float w1 = wp[DIM];
        float w2 = wp[2 * DIM];
        float w3 = wp[3 * DIM];
        #pragma unroll
        for (int m = 0; m < BATCH; m++) {
            float4 xv = xs4[m * 64 + c4];
            acc[m] += xv.x * w0 + xv.y * w1 + xv.z * w2 + xv.w * w3;
        }
    }
    float* o = g_wop + (size_t)blockIdx.y * BATCH * DIM + n;
    #pragma unroll
    for (int m = 0; m < BATCH; m++) o[m * DIM] = acc[m];
}

__global__ __launch_bounds__(256) void k_wo_reduce(float* __restrict__ out) {
    int idx = blockIdx.x * 256 + threadIdx.x;            // < 32*4096
    float s = 0.f;
    #pragma unroll
    for (int p = 0; p < KSPLIT; p++) s += g_wop[(size_t)p * BATCH * DIM + idx];
    out[idx] = s;
}

// ---------------- launch ------------------------------------------------------
extern "C" void kernel_launch(void* const* d_in, const int* in_sizes, int n_in,
                              void* d_out, int out_size) {
    const float* x    = (const float*)d_in[0];
    const float* wqkv = (const float*)d_in[1];
    const float* wo   = (const float*)d_in[2];
    const float* ck   = (const float*)d_in[3];
    const float* cv   = (const float*)d_in[4];
    const int*   sp   = (const int*)d_in[5];
    float*       out  = (float*)d_out;

    k_rope_table<<<1, 64>>>(sp);
    k_qkv<<<dim3(QKVN / 256, KSPLIT), 256>>>(x, wqkv);
    k_reduce_rope<<<(BATCH * QKVN) / 256, 256>>>();
    k_attn<<<dim3(NCH, BATCH * NKV), 128>>>(ck, cv, sp);
    k_combine<<<BATCH * NKV, 128>>>();
    k_wo<<<dim3(DIM / 256, KSPLIT), 256>>>(wo);
    k_wo_reduce<<<(BATCH * DIM) / 256, 256>>>(out);
}